// round 13
// baseline (speedup 1.0000x reference)
#include <cuda_runtime.h>
#include <cuda_fp16.h>
#include <cstdint>

constexpr int CB  = 2;
constexpr int CS  = 2048;
constexpr int CD  = 1024;
constexpr int CH  = 16;
constexpr int CDK = 64;
constexpr int CDFF= 4096;
constexpr int CM  = CB * CS;   // 4096

// ------------------------- scratch (device globals) --------------------------
__device__ __half g_xh [(size_t)CM*CD];
__device__ __half g_wqkvh[(size_t)CD*3*CD];
__device__ __half g_woh[(size_t)CD*CD];
__device__ __half g_w1h[(size_t)CD*CDFF];
__device__ __half g_w2h[(size_t)CDFF*CD];
__device__ __half g_qh [(size_t)CB*CH*CS*CDK];
__device__ __half g_kh [(size_t)CB*CH*CS*CDK];
__device__ __half g_vh [(size_t)CB*CH*CS*CDK];
__device__ __half g_Eh [(size_t)CB*CH*CS*CS];   // normalized attention weights
__device__ __half g_ctxh[(size_t)CM*CD];
__device__ __half g_x1h[(size_t)CM*CD];
__device__ __half g_ffh[(size_t)CM*CDFF];
__device__ float  g_t0 [(size_t)CM*CD];
__device__ float  g_x1 [(size_t)CM*CD];

// ------------------------- helpers ------------------------------------------
__device__ __forceinline__ float fast_exp(float x) {
    const float L2E = 1.4426950408889634f;
    float t = fmaf(x, L2E, 12582912.0f);
    int   e = __float_as_int(t) - 0x4B400000;
    float r = t - 12582912.0f;
    float f = fmaf(x, L2E, -r);
    float p =            1.3333558e-3f;
    p = fmaf(p, f, 9.6181291e-3f);
    p = fmaf(p, f, 5.5504109e-2f);
    p = fmaf(p, f, 2.4022651e-1f);
    p = fmaf(p, f, 6.9314718e-1f);
    p = fmaf(p, f, 1.0f);
    return __int_as_float(__float_as_int(p) + (e << 23));
}
__device__ __forceinline__ uint32_t smem_u32(const void* p) {
    uint32_t a;
    asm("{ .reg .u64 t; cvta.to.shared.u64 t, %1; cvt.u32.u64 %0, t; }" : "=r"(a) : "l"(p));
    return a;
}
__device__ __forceinline__ void cp16(uint32_t dst, const void* src) {
    asm volatile("cp.async.cg.shared.global [%0], [%1], 16;"
                 :: "r"(dst), "l"((unsigned long long)__cvta_generic_to_global(src)));
}
#define CP_COMMIT() asm volatile("cp.async.commit_group;" ::: "memory")
#define CP_WAIT(n)  asm volatile("cp.async.wait_group %0;" :: "n"(n) : "memory")

#define LDSM4(r, a) \
    asm volatile("ldmatrix.sync.aligned.m8n8.x4.shared.b16 {%0,%1,%2,%3}, [%4];" \
        : "=r"((r)[0]), "=r"((r)[1]), "=r"((r)[2]), "=r"((r)[3]) : "r"(a))
#define LDSM4T(r, a) \
    asm volatile("ldmatrix.sync.aligned.m8n8.x4.trans.shared.b16 {%0,%1,%2,%3}, [%4];" \
        : "=r"((r)[0]), "=r"((r)[1]), "=r"((r)[2]), "=r"((r)[3]) : "r"(a))
#define MMA16(c, a, b0, b1) \
    asm volatile("mma.sync.aligned.m16n8k16.row.col.f32.f16.f16.f32 " \
        "{%0,%1,%2,%3},{%4,%5,%6,%7},{%8,%9},{%0,%1,%2,%3};" \
        : "+f"((c)[0]), "+f"((c)[1]), "+f"((c)[2]), "+f"((c)[3]) \
        : "r"((a)[0]), "r"((a)[1]), "r"((a)[2]), "r"((a)[3]), "r"(b0), "r"(b1))

__device__ __forceinline__ uint32_t hmul2u(uint32_t a, uint32_t b) {
    __half2 r = __hmul2(*(__half2*)&a, *(__half2*)&b);
    return *(uint32_t*)&r;
}
__device__ __forceinline__ uint32_t packh2(float a, float b) {
    __half2 h = __floats2half2_rn(a, b);
    return *(uint32_t*)&h;
}

// ------------------------- fused f32 -> f16 convert --------------------------
__global__ void f2h_all(const float* __restrict__ x,
                        const float* __restrict__ wq, const float* __restrict__ wk,
                        const float* __restrict__ wv, const float* __restrict__ wo,
                        const float* __restrict__ w1, const float* __restrict__ w2,
                        __half* __restrict__ xh, __half* __restrict__ wqkvh,
                        __half* __restrict__ woh,
                        __half* __restrict__ w1h, __half* __restrict__ w2h)
{
    const size_t e8 = ((size_t)blockIdx.x * 256 + threadIdx.x) * 8;
    const float* s; __half* d; size_t off, dst;
    if (e8 < 4194304) { s = x; d = xh; off = e8; dst = off; }
    else if (e8 < 7340032) {
        const size_t o = e8 - 4194304;
        const int proj = (int)(o >> 20);
        off = o & 1048575;
        s = proj == 0 ? wq : (proj == 1 ? wk : wv);
        d = wqkvh;
        const size_t k = off >> 10, c = off & 1023;
        dst = k * 3072 + proj * 1024 + c;
    }
    else if (e8 <  8388608) { s = wo; d = woh; off = e8 - 7340032; dst = off; }
    else if (e8 < 12582912) { s = w1; d = w1h; off = e8 - 8388608; dst = off; }
    else                    { s = w2; d = w2h; off = e8 - 12582912; dst = off; }
    float4 u0 = *(const float4*)(s + off);
    float4 u1 = *(const float4*)(s + off + 4);
    __half2 h0 = __floats2half2_rn(u0.x, u0.y);
    __half2 h1 = __floats2half2_rn(u0.z, u0.w);
    __half2 h2 = __floats2half2_rn(u1.x, u1.y);
    __half2 h3 = __floats2half2_rn(u1.z, u1.w);
    uint4 o;
    o.x = *(uint32_t*)&h0; o.y = *(uint32_t*)&h1;
    o.z = *(uint32_t*)&h2; o.w = *(uint32_t*)&h3;
    *(uint4*)(d + dst) = o;
}

// ------------------------- shared dense mainloop (BK=64) ---------------------
constexpr int G_AST = 72, G_BST = 136;
constexpr int G_ASZ = 128 * G_AST, G_BSZ = 64 * G_BST;
constexpr int G_STG = G_ASZ + G_BSZ;

__device__ __forceinline__ void g_issue(uint32_t smb, int tid, int kt,
                                        const __half* A, const __half* W,
                                        int K, int N, int bm, int bn)
{
    const int st = kt % 3;
    const __half* As = A + (size_t)bm * K + kt * 64;
    const __half* Ws = W + (size_t)(kt * 64) * N + bn;
    #pragma unroll
    for (int i = 0; i < 4; i++) {
        const int c = i * 256 + tid;
        const int r = c >> 3, h8 = (c & 7) * 8;
        cp16(smb + (st * G_STG + r * G_AST + h8) * 2, As + (size_t)r * K + h8);
    }
    #pragma unroll
    for (int i = 0; i < 4; i++) {
        const int c = i * 256 + tid;
        const int kk = c >> 4, n8 = (c & 15) * 8;
        cp16(smb + (st * G_STG + G_ASZ + kk * G_BST + n8) * 2, Ws + (size_t)kk * N + n8);
    }
}

__device__ __forceinline__ void g_compute(uint32_t smb, int kt, int lane,
                                          int wm, int wn, float acc[2][8][4])
{
    const uint32_t stA = smb + (kt % 3) * G_STG * 2;
    const uint32_t stB = stA + G_ASZ * 2;
    #pragma unroll
    for (int h16 = 0; h16 < 4; h16++) {
        const int kk16 = h16 * 16;
        uint32_t a[2][4], b[8][2];
        #pragma unroll
        for (int mi = 0; mi < 2; mi++) {
            const uint32_t ad = stA +
                ((wm * 32 + mi * 16 + (lane & 15)) * G_AST + kk16 + (lane >> 4) * 8) * 2;
            LDSM4(a[mi], ad);
        }
        #pragma unroll
        for (int p = 0; p < 4; p++) {
            const int n0 = wn * 64 + p * 16;
            const uint32_t ad = stB +
                ((kk16 + (lane & 7) + ((lane >> 3) & 1) * 8) * G_BST + n0 + (lane >> 4) * 8) * 2;
            uint32_t r[4];
            LDSM4T(r, ad);
            b[2*p  ][0] = r[0]; b[2*p  ][1] = r[1];
            b[2*p+1][0] = r[2]; b[2*p+1][1] = r[3];
        }
        #pragma unroll
        for (int mi = 0; mi < 2; mi++)
            #pragma unroll
            for (int ni = 0; ni < 8; ni++)
                MMA16(acc[mi][ni], a[mi], b[ni][0], b[ni][1]);
    }
}

// ======================= dense GEMM fp16 (BK=64, 3-stage) ====================
template<int OMODE, bool RELU>       // 0: fp32 rm, 2: fp16 rm
__global__ __launch_bounds__(256, 2)
void gemm_h(const __half* __restrict__ A, const __half* __restrict__ W,
            const float* __restrict__ bias, void* __restrict__ Cout,
            int M, int N, int K)
{
    extern __shared__ __half sh[];
    const uint32_t smb = smem_u32(sh);
    const int tid = threadIdx.x, wid = tid >> 5, lane = tid & 31;
    const int wm = wid >> 1, wn = wid & 1;
    const int gid = lane >> 2, tig = lane & 3;
    const int bm = blockIdx.y * 128, bn = blockIdx.x * 128;

    float acc[2][8][4] = {};
    const int nt = K / 64;
    g_issue(smb, tid, 0, A, W, K, N, bm, bn); CP_COMMIT();
    g_issue(smb, tid, 1, A, W, K, N, bm, bn); CP_COMMIT();

    for (int kt = 0; kt < nt; kt++) {
        CP_WAIT(1);
        __syncthreads();
        if (kt + 2 < nt) g_issue(smb, tid, kt + 2, A, W, K, N, bm, bn);
        CP_COMMIT();
        g_compute(smb, kt, lane, wm, wn, acc);
    }

    #pragma unroll
    for (int mi = 0; mi < 2; mi++) {
        #pragma unroll
        for (int ni = 0; ni < 8; ni++) {
            const int row = bm + wm * 32 + mi * 16 + gid;
            const int col = bn + wn * 64 + ni * 8 + tig * 2;
            const float2 b2 = *(const float2*)(bias + col);
            float v0 = acc[mi][ni][0] + b2.x, v1 = acc[mi][ni][1] + b2.y;
            float v2 = acc[mi][ni][2] + b2.x, v3 = acc[mi][ni][3] + b2.y;
            if (RELU) { v0 = fmaxf(v0, 0.f); v1 = fmaxf(v1, 0.f);
                        v2 = fmaxf(v2, 0.f); v3 = fmaxf(v3, 0.f); }
            if (OMODE == 0) {
                float* C = (float*)Cout;
                *(float2*)(C + (size_t)row       * N + col) = make_float2(v0, v1);
                *(float2*)(C + (size_t)(row + 8) * N + col) = make_float2(v2, v3);
            } else {
                __half* C = (__half*)Cout;
                *(__half2*)(C + (size_t)row       * N + col) = __floats2half2_rn(v0, v1);
                *(__half2*)(C + (size_t)(row + 8) * N + col) = __floats2half2_rn(v2, v3);
            }
        }
    }
}

// ======================= fused QKV GEMM (N=3072) =============================
__global__ __launch_bounds__(256, 2)
void gemm_qkv(const __half* __restrict__ A, const __half* __restrict__ W,
              const float* __restrict__ bq, const float* __restrict__ bk,
              const float* __restrict__ bv,
              __half* __restrict__ Oq, __half* __restrict__ Ok,
              __half* __restrict__ Ov)
{
    constexpr int K = CD, N = 3 * CD;
    extern __shared__ __half sh[];
    const uint32_t smb = smem_u32(sh);
    const int tid = threadIdx.x, wid = tid >> 5, lane = tid & 31;
    const int wm = wid >> 1, wn = wid & 1;
    const int gid = lane >> 2, tig = lane & 3;
    const int bm = blockIdx.y * 128, bn = blockIdx.x * 128;

    float acc[2][8][4] = {};
    const int nt = K / 64;
    g_issue(smb, tid, 0, A, W, K, N, bm, bn); CP_COMMIT();
    g_issue(smb, tid, 1, A, W, K, N, bm, bn); CP_COMMIT();

    for (int kt = 0; kt < nt; kt++) {
        CP_WAIT(1);
        __syncthreads();
        if (kt + 2 < nt) g_issue(smb, tid, kt + 2, A, W, K, N, bm, bn);
        CP_COMMIT();
        g_compute(smb, kt, lane, wm, wn, acc);
    }

    const int cb = bn + wn * 64;
    const int proj = cb >> 10;
    const int h = (cb >> 6) & 15;
    __half* O = proj == 0 ? Oq : (proj == 1 ? Ok : Ov);
    const float* bs = proj == 0 ? bq : (proj == 1 ? bk : bv);
    #pragma unroll
    for (int mi = 0; mi < 2; mi++) {
        #pragma unroll
        for (int ni = 0; ni < 8; ni++) {
            const int row = bm + wm * 32 + mi * 16 + gid;
            const int dk = ni * 8 + tig * 2;
            const float2 b2 = *(const float2*)(bs + h * 64 + dk);
            const int b = row >> 11, s1 = row & (CS - 1);
            const size_t base = (((size_t)(b * CH + h)) * CS + s1) * CDK + dk;
            *(__half2*)(O + base) =
                __floats2half2_rn(acc[mi][ni][0] + b2.x, acc[mi][ni][1] + b2.y);
            *(__half2*)(O + base + (size_t)8 * CDK) =
                __floats2half2_rn(acc[mi][ni][2] + b2.x, acc[mi][ni][3] + b2.y);
        }
    }
}

// ======================= scores: normalized E, no rd array ===================
// CTA: (b, q0: 32 rows, k0: 64 cols) for ALL 16 heads. Per-head exp'd fragments
// kept in registers (4 x half2 per head); over-heads sum in fp32 registers.
// After head loop: multiply by 1/sum and write normalized E directly.
__global__ __launch_bounds__(256, 2)
void scorenorm_h()
{
    constexpr int QST = 72;
    constexpr int QSZ = 32 * QST, KSZ = 64 * QST, STG = QSZ + KSZ;  // 6912 halves
    extern __shared__ __half sh[];
    const uint32_t smb = smem_u32(sh);

    const int tid = threadIdx.x, wid = tid >> 5, lane = tid & 31;
    const int wm = wid >> 2, wn = wid & 3;       // 2 m-warps x 4 n-warps
    const int gid = lane >> 2, tig = lane & 3;
    const int b = blockIdx.z;
    const int q0 = blockIdx.y * 32, k0 = blockIdx.x * 64;
    const size_t plane = (size_t)CS * CS;

    auto issue = [&](int h) {
        const int st = h & 1;
        const __half* qb = g_qh + (((size_t)(b * CH + h)) * CS + q0) * CDK;
        const __half* kb = g_kh + (((size_t)(b * CH + h)) * CS + k0) * CDK;
        {   // Q: 32 rows x 64 halves = 256 cp16
            const int r = tid >> 3, h8 = (tid & 7) * 8;
            cp16(smb + (st * STG + r * QST + h8) * 2, qb + (size_t)r * CDK + h8);
        }
        #pragma unroll
        for (int i = 0; i < 2; i++) {           // K: 64 rows = 512 cp16
            const int c = i * 256 + tid;
            const int r = c >> 3, h8 = (c & 7) * 8;
            cp16(smb + (st * STG + QSZ + r * QST + h8) * 2, kb + (size_t)r * CDK + h8);
        }
    };

    uint32_t Ereg[CH][4];
    float sum[8] = {};

    issue(0); CP_COMMIT();

    #pragma unroll
    for (int h = 0; h < CH; h++) {
        if (h + 1 < CH) { issue(h + 1); CP_COMMIT(); CP_WAIT(1); }
        else            { CP_WAIT(0); }
        __syncthreads();

        const uint32_t stQ = smb + (h & 1) * STG * 2;
        const uint32_t stK = stQ + QSZ * 2;

        float acc[8] = {};
        #pragma unroll
        for (int c16 = 0; c16 < 4; c16++) {
            const int kk16 = c16 * 16;
            uint32_t a[4], r[4];
            LDSM4(a, stQ + ((wm * 16 + (lane & 15)) * QST + kk16 + (lane >> 4) * 8) * 2);
            LDSM4(r, stK + ((wn * 16 + (lane & 15)) * QST + kk16 + (lane >> 4) * 8) * 2);
            MMA16(acc + 0, a, r[0], r[2]);
            MMA16(acc + 4, a, r[1], r[3]);
        }

        float e[8];
        #pragma unroll
        for (int j = 0; j < 8; j++) { e[j] = fast_exp(acc[j] * 0.125f); sum[j] += e[j]; }
        Ereg[h][0] = packh2(e[0], e[1]);
        Ereg[h][1] = packh2(e[2], e[3]);
        Ereg[h][2] = packh2(e[4], e[5]);
        Ereg[h][3] = packh2(e[6], e[7]);
        __syncthreads();
    }

    uint32_t rdh2[4];
    rdh2[0] = packh2(1.0f / sum[0], 1.0f / sum[1]);
    rdh2[1] = packh2(1.0f / sum[2], 1.0f / sum[3]);
    rdh2[2] = packh2(1.0f / sum[4], 1.0f / sum[5]);
    rdh2[3] = packh2(1.0f / sum[6], 1.0f / sum[7]);

    const int q = q0 + wm * 16 + gid;
    const int k = k0 + wn * 16 + tig * 2;
    #pragma unroll
    for (int h = 0; h < CH; h++) {
        __half* Eb = g_Eh + ((size_t)(b * CH + h)) * plane;
        *(uint32_t*)(Eb + (size_t)q       * CS + k    ) = hmul2u(Ereg[h][0], rdh2[0]);
        *(uint32_t*)(Eb + (size_t)(q + 8) * CS + k    ) = hmul2u(Ereg[h][1], rdh2[1]);
        *(uint32_t*)(Eb + (size_t)q       * CS + k + 8) = hmul2u(Ereg[h][2], rdh2[2]);
        *(uint32_t*)(Eb + (size_t)(q + 8) * CS + k + 8) = hmul2u(Ereg[h][3], rdh2[3]);
    }
}

// ======================= ctx: E_norm @ V, BK=64, 3-stage =====================
__global__ __launch_bounds__(256, 2)
void ctx_h()
{
    constexpr int EST = 72, VST = 72;
    constexpr int ESZ = 128 * EST, VSZ = 64 * VST;
    constexpr int STG = ESZ + VSZ;                          // 13824 halves
    extern __shared__ __half sh[];
    const uint32_t smb = smem_u32(sh);

    const int tid = threadIdx.x, wid = tid >> 5, lane = tid & 31;
    const int wm = wid >> 1, wn = wid & 1;
    const int gid = lane >> 2, tig = lane & 3;
    const int bh = blockIdx.y;
    const int b = bh >> 4, h = bh & 15;
    const int q0 = blockIdx.x * 128;
    const size_t plane = (size_t)CS * CS;
    const __half* eb = g_Eh + (size_t)bh * plane;
    const __half* vb = g_vh + (size_t)bh * CS * CDK;

    auto issue = [&](int kt) {
        const int st = kt % 3;
        const int kb = kt * 64;
        #pragma unroll
        for (int i = 0; i < 4; i++) {
            const int c = i * 256 + tid;
            const int r = c >> 3, h8 = (c & 7) * 8;
            cp16(smb + (st * STG + r * EST + h8) * 2, eb + (size_t)(q0 + r) * CS + kb + h8);
        }
        #pragma unroll
        for (int i = 0; i < 2; i++) {
            const int c = i * 256 + tid;
            const int kk = c >> 3, n8 = (c & 7) * 8;
            cp16(smb + (st * STG + ESZ + kk * VST + n8) * 2, vb + (size_t)(kb + kk) * CDK + n8);
        }
    };

    float acc[2][4][4] = {};
    const int nt = CS / 64;
    issue(0); CP_COMMIT();
    issue(1); CP_COMMIT();

    for (int kt = 0; kt < nt; kt++) {
        CP_WAIT(1);
        __syncthreads();
        if (kt + 2 < nt) issue(kt + 2);
        CP_COMMIT();

        const uint32_t stE = smb + (kt % 3) * STG * 2;
        const uint32_t stV = stE + ESZ * 2;
        #pragma unroll
        for (int h16 = 0; h16 < 4; h16++) {
            const int kk16 = h16 * 16;
            uint32_t a[2][4], bv[4][2];
            #pragma unroll
            for (int mi = 0; mi < 2; mi++) {
                const uint32_t ad = stE +
                    ((wm * 32 + mi * 16 + (lane & 15)) * EST + kk16 + (lane >> 4) * 8) * 2;
                LDSM4(a[mi], ad);
            }
            #pragma unroll
            for (int p = 0; p < 2; p++) {
                const int n0 = wn * 32 + p * 16;
                const uint32_t ad = stV +
                    ((kk16 + (lane & 7) + ((lane >> 3) & 1) * 8) * VST + n0 + (lane >> 4) * 8) * 2;
                uint32_t r[4];
                LDSM4T(r, ad);
                bv[2*p  ][0] = r[0]; bv[2*p  ][1] = r[1];
                bv[2*p+1][0] = r[2]; bv[2*p+1][1] = r[3];
            }
            #pragma unroll
            for (int mi = 0; mi < 2; mi++)
                #pragma unroll
                for (int ni = 0; ni < 4; ni++)
                    MMA16(acc[mi][ni], a[mi], bv[ni][0], bv[ni][1]);
        }
    }

    #pragma unroll
    for (int mi = 0; mi < 2; mi++) {
        #pragma unroll
        for (int ni = 0; ni < 4; ni++) {
            const int q = q0 + wm * 32 + mi * 16 + gid;
            const int n = wn * 32 + ni * 8 + tig * 2;
            __half* p0p = g_ctxh + (((size_t)(b * CS + q    )) * CH + h) * CDK + n;
            __half* p1p = g_ctxh + (((size_t)(b * CS + q + 8)) * CH + h) * CDK + n;
            *(__half2*)p0p = __floats2half2_rn(acc[mi][ni][0], acc[mi][ni][1]);
            *(__half2*)p1p = __floats2half2_rn(acc[mi][ni][2], acc[mi][ni][3]);
        }
    }
}

// ------------------------- residual + LayerNorm ------------------------------
__global__ void ln_kernel(const float* __restrict__ A, const float* __restrict__ Bp,
                          const float* __restrict__ g, const float* __restrict__ be,
                          float* __restrict__ out, __half* __restrict__ outh)
{
    const int row = blockIdx.x;
    const int tid = threadIdx.x;
    const int i0 = tid << 2;
    float4 a  = *(const float4*)(A  + (size_t)row*CD + i0);
    float4 bb = *(const float4*)(Bp + (size_t)row*CD + i0);
    const float v0 = a.x + bb.x, v1 = a.y + bb.y, v2 = a.z + bb.z, v3 = a.w + bb.w;
    float s  = v0 + v1 + v2 + v3;
    float ss = v0*v0 + v1*v1 + v2*v2 + v3*v3;
    #pragma unroll
    for (int o = 16; o; o >>= 1) {
        s  += __shfl_xor_sync(0xffffffffu, s,  o);
        ss += __shfl_xor_sync(0xffffffffu, ss, o);
    }
    __shared__ float sh1[8], sh2[8];
    if ((tid & 31) == 0) { sh1[tid >> 5] = s; sh2[tid >> 5] = ss; }
    __syncthreads();
    s = 0.f; ss = 0.f;
    #pragma unroll
    for (int w = 0; w < 8; w++) { s += sh1[w]; ss += sh2[w]; }
    const float mean = s * (1.0f / CD);
    const float var  = ss * (1.0f / CD) - mean * mean;
    const float rstd = rsqrtf(var + 1e-5f);
    float4 gg = *(const float4*)(g  + i0);
    float4 bt = *(const float4*)(be + i0);
    float4 o4;
    o4.x = (v0 - mean) * rstd * gg.x + bt.x;
    o4.y = (v1 - mean) * rstd * gg.y + bt.y;
    o4.z = (v2 - mean) * rstd * gg.z + bt.z;
    o4.w = (v3 - mean) * rstd * gg.w + bt.w;
    *(float4*)(out + (size_t)row*CD + i0) = o4;
    if (outh) {
        __half2 h0 = __floats2half2_rn(o4.x, o4.y);
        __half2 h1 = __floats2half2_rn(o4.z, o4.w);
        uint2 u; u.x = *(uint32_t*)&h0; u.y = *(uint32_t*)&h1;
        *(uint2*)(outh + (size_t)row*CD + i0) = u;
    }
}

// ------------------------- launch -------------------------------------------
extern "C" void kernel_launch(void* const* d_in, const int* in_sizes, int n_in,
                              void* d_out, int out_size)
{
    (void)in_sizes; (void)n_in; (void)out_size;
    const float* x   = (const float*)d_in[0];
    const float* wq  = (const float*)d_in[1];
    const float* bq  = (const float*)d_in[2];
    const float* wk  = (const float*)d_in[3];
    const float* bk  = (const float*)d_in[4];
    const float* wv  = (const float*)d_in[5];
    const float* bv  = (const float*)d_in[6];
    const float* wo  = (const float*)d_in[7];
    const float* bo  = (const float*)d_in[8];
    const float* g1  = (const float*)d_in[9];
    const float* be1 = (const float*)d_in[10];
    const float* w1  = (const float*)d_in[11];
    const float* b1  = (const float*)d_in[12];
    const float* w2  = (const float*)d_in[13];
    const float* b2  = (const float*)d_in[14];
    const float* g2  = (const float*)d_in[15];
    const float* be2 = (const float*)d_in[16];
    float* out = (float*)d_out;

    __half *pxh, *pwqkvh, *pwoh, *pw1h, *pw2h;
    __half *pqh, *pkh, *pvh, *pctxh, *px1h, *pffh;
    float *pt0, *px1;
    cudaGetSymbolAddress((void**)&pxh,    g_xh);
    cudaGetSymbolAddress((void**)&pwqkvh, g_wqkvh);
    cudaGetSymbolAddress((void**)&pwoh,   g_woh);
    cudaGetSymbolAddress((void**)&pw1h,   g_w1h);
    cudaGetSymbolAddress((void**)&pw2h,   g_w2h);
    cudaGetSymbolAddress((void**)&pqh,    g_qh);
    cudaGetSymbolAddress((void**)&pkh,    g_kh);
    cudaGetSymbolAddress((void**)&pvh,    g_vh);
    cudaGetSymbolAddress((void**)&pctxh,  g_ctxh);
    cudaGetSymbolAddress((void**)&px1h,   g_x1h);
    cudaGetSymbolAddress((void**)&pffh,   g_ffh);
    cudaGetSymbolAddress((void**)&pt0,    g_t0);
    cudaGetSymbolAddress((void**)&px1,    g_x1);

    const int SMEM_G = 3 * G_STG * 2;                    // 107520
    const int SMEM_S = 2 * (96 * 72) * 2;                // 27648
    const int SMEM_C = 3 * (128 * 72 + 64 * 72) * 2;     // 82944
    cudaFuncSetAttribute(gemm_h<0,false>, cudaFuncAttributeMaxDynamicSharedMemorySize, SMEM_G);
    cudaFuncSetAttribute(gemm_h<2,true >, cudaFuncAttributeMaxDynamicSharedMemorySize, SMEM_G);
    cudaFuncSetAttribute(gemm_qkv,   cudaFuncAttributeMaxDynamicSharedMemorySize, SMEM_G);
    cudaFuncSetAttribute(scorenorm_h, cudaFuncAttributeMaxDynamicSharedMemorySize, SMEM_S);
    cudaFuncSetAttribute(ctx_h,      cudaFuncAttributeMaxDynamicSharedMemorySize, SMEM_C);

    f2h_all<<<8192, 256>>>(x, wq, wk, wv, wo, w1, w2,
                           pxh, pwqkvh, pwoh, pw1h, pw2h);

    gemm_qkv<<<dim3(3*CD/128, CM/128), 256, SMEM_G>>>(pxh, pwqkvh, bq, bk, bv,
                                                      pqh, pkh, pvh);

    scorenorm_h<<<dim3(CS/64, CS/32, CB), 256, SMEM_S>>>();
    ctx_h<<<dim3(CS/128, CB*CH), 256, SMEM_C>>>();

    const dim3 gDD(CD / 128, CM / 128);
    gemm_h<0, false><<<gDD, 256, SMEM_G>>>(pctxh, pwoh, bo, pt0, CM, CD, CD);
    ln_kernel<<<CM, 256>>>(x, pt0, g1, be1, px1, px1h);

    gemm_h<2, true ><<<dim3(CDFF/128, CM/128), 256, SMEM_G>>>(px1h, pw1h, b1, pffh, CM, CDFF, CD);
    gemm_h<0, false><<<gDD, 256, SMEM_G>>>(pffh, pw2h, b2, pt0, CM, CD, CDFF);
    ln_kernel<<<CM, 256>>>(px1, pt0, g2, be2, out, nullptr);
}

// round 14
// speedup vs baseline: 1.0735x; 1.0735x over previous
#include <cuda_runtime.h>
#include <cuda_fp16.h>
#include <cstdint>

constexpr int CB  = 2;
constexpr int CS  = 2048;
constexpr int CD  = 1024;
constexpr int CH  = 16;
constexpr int CDK = 64;
constexpr int CDFF= 4096;
constexpr int CM  = CB * CS;   // 4096

// ------------------------- scratch (device globals) --------------------------
__device__ __half g_xh [(size_t)CM*CD];
__device__ __half g_wqkvh[(size_t)CD*3*CD];
__device__ __half g_woh[(size_t)CD*CD];
__device__ __half g_w1h[(size_t)CD*CDFF];
__device__ __half g_w2h[(size_t)CDFF*CD];
__device__ __half g_qh [(size_t)CB*CH*CS*CDK];
__device__ __half g_kh [(size_t)CB*CH*CS*CDK];
__device__ __half g_vh [(size_t)CB*CH*CS*CDK];
__device__ __half g_Eh [(size_t)CB*CH*CS*CS];   // normalized attention weights
__device__ __half g_ctxh[(size_t)CM*CD];
__device__ __half g_x1h[(size_t)CM*CD];
__device__ __half g_ffh[(size_t)CM*CDFF];
__device__ float  g_t0 [(size_t)CM*CD];
__device__ float  g_x1 [(size_t)CM*CD];

// ------------------------- helpers ------------------------------------------
__device__ __forceinline__ float fast_exp(float x) {
    const float L2E = 1.4426950408889634f;
    float t = fmaf(x, L2E, 12582912.0f);
    int   e = __float_as_int(t) - 0x4B400000;
    float r = t - 12582912.0f;
    float f = fmaf(x, L2E, -r);
    float p =            1.3333558e-3f;
    p = fmaf(p, f, 9.6181291e-3f);
    p = fmaf(p, f, 5.5504109e-2f);
    p = fmaf(p, f, 2.4022651e-1f);
    p = fmaf(p, f, 6.9314718e-1f);
    p = fmaf(p, f, 1.0f);
    return __int_as_float(__float_as_int(p) + (e << 23));
}
__device__ __forceinline__ uint32_t smem_u32(const void* p) {
    uint32_t a;
    asm("{ .reg .u64 t; cvta.to.shared.u64 t, %1; cvt.u32.u64 %0, t; }" : "=r"(a) : "l"(p));
    return a;
}
__device__ __forceinline__ void cp16(uint32_t dst, const void* src) {
    asm volatile("cp.async.cg.shared.global [%0], [%1], 16;"
                 :: "r"(dst), "l"((unsigned long long)__cvta_generic_to_global(src)));
}
__device__ __forceinline__ void st16cs(void* p, uint4 v) {
    asm volatile("st.global.cs.v4.b32 [%0], {%1,%2,%3,%4};"
                 :: "l"(__cvta_generic_to_global(p)),
                    "r"(v.x), "r"(v.y), "r"(v.z), "r"(v.w) : "memory");
}
#define CP_COMMIT() asm volatile("cp.async.commit_group;" ::: "memory")
#define CP_WAIT(n)  asm volatile("cp.async.wait_group %0;" :: "n"(n) : "memory")

#define LDSM4(r, a) \
    asm volatile("ldmatrix.sync.aligned.m8n8.x4.shared.b16 {%0,%1,%2,%3}, [%4];" \
        : "=r"((r)[0]), "=r"((r)[1]), "=r"((r)[2]), "=r"((r)[3]) : "r"(a))
#define LDSM4T(r, a) \
    asm volatile("ldmatrix.sync.aligned.m8n8.x4.trans.shared.b16 {%0,%1,%2,%3}, [%4];" \
        : "=r"((r)[0]), "=r"((r)[1]), "=r"((r)[2]), "=r"((r)[3]) : "r"(a))
#define MMA16(c, a, b0, b1) \
    asm volatile("mma.sync.aligned.m16n8k16.row.col.f32.f16.f16.f32 " \
        "{%0,%1,%2,%3},{%4,%5,%6,%7},{%8,%9},{%0,%1,%2,%3};" \
        : "+f"((c)[0]), "+f"((c)[1]), "+f"((c)[2]), "+f"((c)[3]) \
        : "r"((a)[0]), "r"((a)[1]), "r"((a)[2]), "r"((a)[3]), "r"(b0), "r"(b1))

__device__ __forceinline__ uint32_t hmul2u(uint32_t a, uint32_t b) {
    __half2 r = __hmul2(*(__half2*)&a, *(__half2*)&b);
    return *(uint32_t*)&r;
}
__device__ __forceinline__ uint32_t packh2(float a, float b) {
    __half2 h = __floats2half2_rn(a, b);
    return *(uint32_t*)&h;
}

// ------------------------- fused f32 -> f16 convert --------------------------
__global__ void f2h_all(const float* __restrict__ x,
                        const float* __restrict__ wq, const float* __restrict__ wk,
                        const float* __restrict__ wv, const float* __restrict__ wo,
                        const float* __restrict__ w1, const float* __restrict__ w2,
                        __half* __restrict__ xh, __half* __restrict__ wqkvh,
                        __half* __restrict__ woh,
                        __half* __restrict__ w1h, __half* __restrict__ w2h)
{
    const size_t e8 = ((size_t)blockIdx.x * 256 + threadIdx.x) * 8;
    const float* s; __half* d; size_t off, dst;
    if (e8 < 4194304) { s = x; d = xh; off = e8; dst = off; }
    else if (e8 < 7340032) {
        const size_t o = e8 - 4194304;
        const int proj = (int)(o >> 20);
        off = o & 1048575;
        s = proj == 0 ? wq : (proj == 1 ? wk : wv);
        d = wqkvh;
        const size_t k = off >> 10, c = off & 1023;
        dst = k * 3072 + proj * 1024 + c;
    }
    else if (e8 <  8388608) { s = wo; d = woh; off = e8 - 7340032; dst = off; }
    else if (e8 < 12582912) { s = w1; d = w1h; off = e8 - 8388608; dst = off; }
    else                    { s = w2; d = w2h; off = e8 - 12582912; dst = off; }
    float4 u0 = *(const float4*)(s + off);
    float4 u1 = *(const float4*)(s + off + 4);
    __half2 h0 = __floats2half2_rn(u0.x, u0.y);
    __half2 h1 = __floats2half2_rn(u0.z, u0.w);
    __half2 h2 = __floats2half2_rn(u1.x, u1.y);
    __half2 h3 = __floats2half2_rn(u1.z, u1.w);
    uint4 o;
    o.x = *(uint32_t*)&h0; o.y = *(uint32_t*)&h1;
    o.z = *(uint32_t*)&h2; o.w = *(uint32_t*)&h3;
    *(uint4*)(d + dst) = o;
}

// ------------------------- shared dense mainloop (BK=64) ---------------------
constexpr int G_AST = 72, G_BST = 136;
constexpr int G_ASZ = 128 * G_AST, G_BSZ = 64 * G_BST;
constexpr int G_STG = G_ASZ + G_BSZ;

__device__ __forceinline__ void g_issue(uint32_t smb, int tid, int kt,
                                        const __half* A, const __half* W,
                                        int K, int N, int bm, int bn)
{
    const int st = kt % 3;
    const __half* As = A + (size_t)bm * K + kt * 64;
    const __half* Ws = W + (size_t)(kt * 64) * N + bn;
    #pragma unroll
    for (int i = 0; i < 4; i++) {
        const int c = i * 256 + tid;
        const int r = c >> 3, h8 = (c & 7) * 8;
        cp16(smb + (st * G_STG + r * G_AST + h8) * 2, As + (size_t)r * K + h8);
    }
    #pragma unroll
    for (int i = 0; i < 4; i++) {
        const int c = i * 256 + tid;
        const int kk = c >> 4, n8 = (c & 15) * 8;
        cp16(smb + (st * G_STG + G_ASZ + kk * G_BST + n8) * 2, Ws + (size_t)kk * N + n8);
    }
}

__device__ __forceinline__ void g_compute(uint32_t smb, int kt, int lane,
                                          int wm, int wn, float acc[2][8][4])
{
    const uint32_t stA = smb + (kt % 3) * G_STG * 2;
    const uint32_t stB = stA + G_ASZ * 2;
    #pragma unroll
    for (int h16 = 0; h16 < 4; h16++) {
        const int kk16 = h16 * 16;
        uint32_t a[2][4], b[8][2];
        #pragma unroll
        for (int mi = 0; mi < 2; mi++) {
            const uint32_t ad = stA +
                ((wm * 32 + mi * 16 + (lane & 15)) * G_AST + kk16 + (lane >> 4) * 8) * 2;
            LDSM4(a[mi], ad);
        }
        #pragma unroll
        for (int p = 0; p < 4; p++) {
            const int n0 = wn * 64 + p * 16;
            const uint32_t ad = stB +
                ((kk16 + (lane & 7) + ((lane >> 3) & 1) * 8) * G_BST + n0 + (lane >> 4) * 8) * 2;
            uint32_t r[4];
            LDSM4T(r, ad);
            b[2*p  ][0] = r[0]; b[2*p  ][1] = r[1];
            b[2*p+1][0] = r[2]; b[2*p+1][1] = r[3];
        }
        #pragma unroll
        for (int mi = 0; mi < 2; mi++)
            #pragma unroll
            for (int ni = 0; ni < 8; ni++)
                MMA16(acc[mi][ni], a[mi], b[ni][0], b[ni][1]);
    }
}

// ======================= dense GEMM fp16 (BK=64, 3-stage) ====================
template<int OMODE, bool RELU>       // 0: fp32 rm, 2: fp16 rm
__global__ __launch_bounds__(256, 2)
void gemm_h(const __half* __restrict__ A, const __half* __restrict__ W,
            const float* __restrict__ bias, void* __restrict__ Cout,
            int M, int N, int K)
{
    extern __shared__ __half sh[];
    const uint32_t smb = smem_u32(sh);
    const int tid = threadIdx.x, wid = tid >> 5, lane = tid & 31;
    const int wm = wid >> 1, wn = wid & 1;
    const int gid = lane >> 2, tig = lane & 3;
    const int bm = blockIdx.y * 128, bn = blockIdx.x * 128;

    float acc[2][8][4] = {};
    const int nt = K / 64;
    g_issue(smb, tid, 0, A, W, K, N, bm, bn); CP_COMMIT();
    g_issue(smb, tid, 1, A, W, K, N, bm, bn); CP_COMMIT();

    for (int kt = 0; kt < nt; kt++) {
        CP_WAIT(1);
        __syncthreads();
        if (kt + 2 < nt) g_issue(smb, tid, kt + 2, A, W, K, N, bm, bn);
        CP_COMMIT();
        g_compute(smb, kt, lane, wm, wn, acc);
    }

    #pragma unroll
    for (int mi = 0; mi < 2; mi++) {
        #pragma unroll
        for (int ni = 0; ni < 8; ni++) {
            const int row = bm + wm * 32 + mi * 16 + gid;
            const int col = bn + wn * 64 + ni * 8 + tig * 2;
            const float2 b2 = *(const float2*)(bias + col);
            float v0 = acc[mi][ni][0] + b2.x, v1 = acc[mi][ni][1] + b2.y;
            float v2 = acc[mi][ni][2] + b2.x, v3 = acc[mi][ni][3] + b2.y;
            if (RELU) { v0 = fmaxf(v0, 0.f); v1 = fmaxf(v1, 0.f);
                        v2 = fmaxf(v2, 0.f); v3 = fmaxf(v3, 0.f); }
            if (OMODE == 0) {
                float* C = (float*)Cout;
                *(float2*)(C + (size_t)row       * N + col) = make_float2(v0, v1);
                *(float2*)(C + (size_t)(row + 8) * N + col) = make_float2(v2, v3);
            } else {
                __half* C = (__half*)Cout;
                *(__half2*)(C + (size_t)row       * N + col) = __floats2half2_rn(v0, v1);
                *(__half2*)(C + (size_t)(row + 8) * N + col) = __floats2half2_rn(v2, v3);
            }
        }
    }
}

// ======================= fused QKV GEMM (N=3072) =============================
__global__ __launch_bounds__(256, 2)
void gemm_qkv(const __half* __restrict__ A, const __half* __restrict__ W,
              const float* __restrict__ bq, const float* __restrict__ bk,
              const float* __restrict__ bv,
              __half* __restrict__ Oq, __half* __restrict__ Ok,
              __half* __restrict__ Ov)
{
    constexpr int K = CD, N = 3 * CD;
    extern __shared__ __half sh[];
    const uint32_t smb = smem_u32(sh);
    const int tid = threadIdx.x, wid = tid >> 5, lane = tid & 31;
    const int wm = wid >> 1, wn = wid & 1;
    const int gid = lane >> 2, tig = lane & 3;
    const int bm = blockIdx.y * 128, bn = blockIdx.x * 128;

    float acc[2][8][4] = {};
    const int nt = K / 64;
    g_issue(smb, tid, 0, A, W, K, N, bm, bn); CP_COMMIT();
    g_issue(smb, tid, 1, A, W, K, N, bm, bn); CP_COMMIT();

    for (int kt = 0; kt < nt; kt++) {
        CP_WAIT(1);
        __syncthreads();
        if (kt + 2 < nt) g_issue(smb, tid, kt + 2, A, W, K, N, bm, bn);
        CP_COMMIT();
        g_compute(smb, kt, lane, wm, wn, acc);
    }

    const int cb = bn + wn * 64;
    const int proj = cb >> 10;
    const int h = (cb >> 6) & 15;
    __half* O = proj == 0 ? Oq : (proj == 1 ? Ok : Ov);
    const float* bs = proj == 0 ? bq : (proj == 1 ? bk : bv);
    #pragma unroll
    for (int mi = 0; mi < 2; mi++) {
        #pragma unroll
        for (int ni = 0; ni < 8; ni++) {
            const int row = bm + wm * 32 + mi * 16 + gid;
            const int dk = ni * 8 + tig * 2;
            const float2 b2 = *(const float2*)(bs + h * 64 + dk);
            const int b = row >> 11, s1 = row & (CS - 1);
            const size_t base = (((size_t)(b * CH + h)) * CS + s1) * CDK + dk;
            *(__half2*)(O + base) =
                __floats2half2_rn(acc[mi][ni][0] + b2.x, acc[mi][ni][1] + b2.y);
            *(__half2*)(O + base + (size_t)8 * CDK) =
                __floats2half2_rn(acc[mi][ni][2] + b2.x, acc[mi][ni][3] + b2.y);
        }
    }
}

// ======================= scores: normalized E, coalesced store ===============
// CTA: (b, q0: 32 rows, k0: 64 cols) for ALL 16 heads. Per-head exp'd fragments
// in registers; over-heads sum in fp32 regs. After head loop: normalize, stage
// each head tile through smem, and store full 128B rows with st.global.cs.
__global__ __launch_bounds__(256, 2)
void scorenorm_h()
{
    constexpr int QST = 72;
    constexpr int QSZ = 32 * QST, KSZ = 64 * QST, STG = QSZ + KSZ;  // 6912 halves
    constexpr int EBUF = 32 * 72;                                   // halves
    extern __shared__ __half sh[];
    const uint32_t smb = smem_u32(sh);

    const int tid = threadIdx.x, wid = tid >> 5, lane = tid & 31;
    const int wm = wid >> 2, wn = wid & 3;       // 2 m-warps x 4 n-warps
    const int gid = lane >> 2, tig = lane & 3;
    const int b = blockIdx.z;
    const int q0 = blockIdx.y * 32, k0 = blockIdx.x * 64;
    const size_t plane = (size_t)CS * CS;

    auto issue = [&](int h) {
        const int st = h & 1;
        const __half* qb = g_qh + (((size_t)(b * CH + h)) * CS + q0) * CDK;
        const __half* kb = g_kh + (((size_t)(b * CH + h)) * CS + k0) * CDK;
        {
            const int r = tid >> 3, h8 = (tid & 7) * 8;
            cp16(smb + (st * STG + r * QST + h8) * 2, qb + (size_t)r * CDK + h8);
        }
        #pragma unroll
        for (int i = 0; i < 2; i++) {
            const int c = i * 256 + tid;
            const int r = c >> 3, h8 = (c & 7) * 8;
            cp16(smb + (st * STG + QSZ + r * QST + h8) * 2, kb + (size_t)r * CDK + h8);
        }
    };

    uint32_t Ereg[CH][4];
    float sum[8] = {};

    issue(0); CP_COMMIT();

    #pragma unroll
    for (int h = 0; h < CH; h++) {
        if (h + 1 < CH) { issue(h + 1); CP_COMMIT(); CP_WAIT(1); }
        else            { CP_WAIT(0); }
        __syncthreads();

        const uint32_t stQ = smb + (h & 1) * STG * 2;
        const uint32_t stK = stQ + QSZ * 2;

        float acc[8] = {};
        #pragma unroll
        for (int c16 = 0; c16 < 4; c16++) {
            const int kk16 = c16 * 16;
            uint32_t a[4], r[4];
            LDSM4(a, stQ + ((wm * 16 + (lane & 15)) * QST + kk16 + (lane >> 4) * 8) * 2);
            LDSM4(r, stK + ((wn * 16 + (lane & 15)) * QST + kk16 + (lane >> 4) * 8) * 2);
            MMA16(acc + 0, a, r[0], r[2]);
            MMA16(acc + 4, a, r[1], r[3]);
        }

        float e[8];
        #pragma unroll
        for (int j = 0; j < 8; j++) { e[j] = fast_exp(acc[j] * 0.125f); sum[j] += e[j]; }
        Ereg[h][0] = packh2(e[0], e[1]);
        Ereg[h][1] = packh2(e[2], e[3]);
        Ereg[h][2] = packh2(e[4], e[5]);
        Ereg[h][3] = packh2(e[6], e[7]);
        __syncthreads();
    }

    uint32_t rdh2[4];
    rdh2[0] = packh2(1.0f / sum[0], 1.0f / sum[1]);
    rdh2[1] = packh2(1.0f / sum[2], 1.0f / sum[3]);
    rdh2[2] = packh2(1.0f / sum[4], 1.0f / sum[5]);
    rdh2[3] = packh2(1.0f / sum[6], 1.0f / sum[7]);

    // staged, coalesced E store: per head, STS fragments then STG 128B rows
    const int ql = wm * 16 + gid;                 // fragment row 0..31
    const int kl = wn * 16 + tig * 2;             // fragment col
    const int srow = tid >> 3, scol = (tid & 7) * 8;
    #pragma unroll
    for (int h = 0; h < CH; h++) {
        __half* eb0 = sh + 2 * STG + (h & 1) * EBUF;
        *(uint32_t*)(eb0 + ql      * 72 + kl    ) = hmul2u(Ereg[h][0], rdh2[0]);
        *(uint32_t*)(eb0 + (ql + 8)* 72 + kl    ) = hmul2u(Ereg[h][1], rdh2[1]);
        *(uint32_t*)(eb0 + ql      * 72 + kl + 8) = hmul2u(Ereg[h][2], rdh2[2]);
        *(uint32_t*)(eb0 + (ql + 8)* 72 + kl + 8) = hmul2u(Ereg[h][3], rdh2[3]);
        __syncthreads();
        __half* Eb = g_Eh + ((size_t)(b * CH + h)) * plane;
        uint4 v = *(uint4*)(eb0 + srow * 72 + scol);
        st16cs(Eb + (size_t)(q0 + srow) * CS + k0 + scol, v);
    }
}

// ======================= ctx: E_norm @ V, BK=64, 3-stage =====================
__global__ __launch_bounds__(256, 2)
void ctx_h()
{
    constexpr int EST = 72, VST = 72;
    constexpr int ESZ = 128 * EST, VSZ = 64 * VST;
    constexpr int STG = ESZ + VSZ;                          // 13824 halves
    extern __shared__ __half sh[];
    const uint32_t smb = smem_u32(sh);

    const int tid = threadIdx.x, wid = tid >> 5, lane = tid & 31;
    const int wm = wid >> 1, wn = wid & 1;
    const int gid = lane >> 2, tig = lane & 3;
    const int bh = blockIdx.y;
    const int b = bh >> 4, h = bh & 15;
    const int q0 = blockIdx.x * 128;
    const size_t plane = (size_t)CS * CS;
    const __half* eb = g_Eh + (size_t)bh * plane;
    const __half* vb = g_vh + (size_t)bh * CS * CDK;

    auto issue = [&](int kt) {
        const int st = kt % 3;
        const int kb = kt * 64;
        #pragma unroll
        for (int i = 0; i < 4; i++) {
            const int c = i * 256 + tid;
            const int r = c >> 3, h8 = (c & 7) * 8;
            cp16(smb + (st * STG + r * EST + h8) * 2, eb + (size_t)(q0 + r) * CS + kb + h8);
        }
        #pragma unroll
        for (int i = 0; i < 2; i++) {
            const int c = i * 256 + tid;
            const int kk = c >> 3, n8 = (c & 7) * 8;
            cp16(smb + (st * STG + ESZ + kk * VST + n8) * 2, vb + (size_t)(kb + kk) * CDK + n8);
        }
    };

    float acc[2][4][4] = {};
    const int nt = CS / 64;
    issue(0); CP_COMMIT();
    issue(1); CP_COMMIT();

    for (int kt = 0; kt < nt; kt++) {
        CP_WAIT(1);
        __syncthreads();
        if (kt + 2 < nt) issue(kt + 2);
        CP_COMMIT();

        const uint32_t stE = smb + (kt % 3) * STG * 2;
        const uint32_t stV = stE + ESZ * 2;
        #pragma unroll
        for (int h16 = 0; h16 < 4; h16++) {
            const int kk16 = h16 * 16;
            uint32_t a[2][4], bv[4][2];
            #pragma unroll
            for (int mi = 0; mi < 2; mi++) {
                const uint32_t ad = stE +
                    ((wm * 32 + mi * 16 + (lane & 15)) * EST + kk16 + (lane >> 4) * 8) * 2;
                LDSM4(a[mi], ad);
            }
            #pragma unroll
            for (int p = 0; p < 2; p++) {
                const int n0 = wn * 32 + p * 16;
                const uint32_t ad = stV +
                    ((kk16 + (lane & 7) + ((lane >> 3) & 1) * 8) * VST + n0 + (lane >> 4) * 8) * 2;
                uint32_t r[4];
                LDSM4T(r, ad);
                bv[2*p  ][0] = r[0]; bv[2*p  ][1] = r[1];
                bv[2*p+1][0] = r[2]; bv[2*p+1][1] = r[3];
            }
            #pragma unroll
            for (int mi = 0; mi < 2; mi++)
                #pragma unroll
                for (int ni = 0; ni < 4; ni++)
                    MMA16(acc[mi][ni], a[mi], bv[ni][0], bv[ni][1]);
        }
    }

    #pragma unroll
    for (int mi = 0; mi < 2; mi++) {
        #pragma unroll
        for (int ni = 0; ni < 4; ni++) {
            const int q = q0 + wm * 32 + mi * 16 + gid;
            const int n = wn * 32 + ni * 8 + tig * 2;
            __half* p0p = g_ctxh + (((size_t)(b * CS + q    )) * CH + h) * CDK + n;
            __half* p1p = g_ctxh + (((size_t)(b * CS + q + 8)) * CH + h) * CDK + n;
            *(__half2*)p0p = __floats2half2_rn(acc[mi][ni][0], acc[mi][ni][1]);
            *(__half2*)p1p = __floats2half2_rn(acc[mi][ni][2], acc[mi][ni][3]);
        }
    }
}

// ------------------------- residual + LayerNorm ------------------------------
__global__ void ln_kernel(const float* __restrict__ A, const float* __restrict__ Bp,
                          const float* __restrict__ g, const float* __restrict__ be,
                          float* __restrict__ out, __half* __restrict__ outh)
{
    const int row = blockIdx.x;
    const int tid = threadIdx.x;
    const int i0 = tid << 2;
    float4 a  = *(const float4*)(A  + (size_t)row*CD + i0);
    float4 bb = *(const float4*)(Bp + (size_t)row*CD + i0);
    const float v0 = a.x + bb.x, v1 = a.y + bb.y, v2 = a.z + bb.z, v3 = a.w + bb.w;
    float s  = v0 + v1 + v2 + v3;
    float ss = v0*v0 + v1*v1 + v2*v2 + v3*v3;
    #pragma unroll
    for (int o = 16; o; o >>= 1) {
        s  += __shfl_xor_sync(0xffffffffu, s,  o);
        ss += __shfl_xor_sync(0xffffffffu, ss, o);
    }
    __shared__ float sh1[8], sh2[8];
    if ((tid & 31) == 0) { sh1[tid >> 5] = s; sh2[tid >> 5] = ss; }
    __syncthreads();
    s = 0.f; ss = 0.f;
    #pragma unroll
    for (int w = 0; w < 8; w++) { s += sh1[w]; ss += sh2[w]; }
    const float mean = s * (1.0f / CD);
    const float var  = ss * (1.0f / CD) - mean * mean;
    const float rstd = rsqrtf(var + 1e-5f);
    float4 gg = *(const float4*)(g  + i0);
    float4 bt = *(const float4*)(be + i0);
    float4 o4;
    o4.x = (v0 - mean) * rstd * gg.x + bt.x;
    o4.y = (v1 - mean) * rstd * gg.y + bt.y;
    o4.z = (v2 - mean) * rstd * gg.z + bt.z;
    o4.w = (v3 - mean) * rstd * gg.w + bt.w;
    *(float4*)(out + (size_t)row*CD + i0) = o4;
    if (outh) {
        __half2 h0 = __floats2half2_rn(o4.x, o4.y);
        __half2 h1 = __floats2half2_rn(o4.z, o4.w);
        uint2 u; u.x = *(uint32_t*)&h0; u.y = *(uint32_t*)&h1;
        *(uint2*)(outh + (size_t)row*CD + i0) = u;
    }
}

// ------------------------- launch -------------------------------------------
extern "C" void kernel_launch(void* const* d_in, const int* in_sizes, int n_in,
                              void* d_out, int out_size)
{
    (void)in_sizes; (void)n_in; (void)out_size;
    const float* x   = (const float*)d_in[0];
    const float* wq  = (const float*)d_in[1];
    const float* bq  = (const float*)d_in[2];
    const float* wk  = (const float*)d_in[3];
    const float* bk  = (const float*)d_in[4];
    const float* wv  = (const float*)d_in[5];
    const float* bv  = (const float*)d_in[6];
    const float* wo  = (const float*)d_in[7];
    const float* bo  = (const float*)d_in[8];
    const float* g1  = (const float*)d_in[9];
    const float* be1 = (const float*)d_in[10];
    const float* w1  = (const float*)d_in[11];
    const float* b1  = (const float*)d_in[12];
    const float* w2  = (const float*)d_in[13];
    const float* b2  = (const float*)d_in[14];
    const float* g2  = (const float*)d_in[15];
    const float* be2 = (const float*)d_in[16];
    float* out = (float*)d_out;

    __half *pxh, *pwqkvh, *pwoh, *pw1h, *pw2h;
    __half *pqh, *pkh, *pvh, *pctxh, *px1h, *pffh;
    float *pt0, *px1;
    cudaGetSymbolAddress((void**)&pxh,    g_xh);
    cudaGetSymbolAddress((void**)&pwqkvh, g_wqkvh);
    cudaGetSymbolAddress((void**)&pwoh,   g_woh);
    cudaGetSymbolAddress((void**)&pw1h,   g_w1h);
    cudaGetSymbolAddress((void**)&pw2h,   g_w2h);
    cudaGetSymbolAddress((void**)&pqh,    g_qh);
    cudaGetSymbolAddress((void**)&pkh,    g_kh);
    cudaGetSymbolAddress((void**)&pvh,    g_vh);
    cudaGetSymbolAddress((void**)&pctxh,  g_ctxh);
    cudaGetSymbolAddress((void**)&px1h,   g_x1h);
    cudaGetSymbolAddress((void**)&pffh,   g_ffh);
    cudaGetSymbolAddress((void**)&pt0,    g_t0);
    cudaGetSymbolAddress((void**)&px1,    g_x1);

    const int SMEM_G = 3 * G_STG * 2;                    // 107520
    const int SMEM_S = (2 * (96 * 72) + 2 * (32 * 72)) * 2;  // 36864
    const int SMEM_C = 3 * (128 * 72 + 64 * 72) * 2;     // 82944
    cudaFuncSetAttribute(gemm_h<0,false>, cudaFuncAttributeMaxDynamicSharedMemorySize, SMEM_G);
    cudaFuncSetAttribute(gemm_h<2,true >, cudaFuncAttributeMaxDynamicSharedMemorySize, SMEM_G);
    cudaFuncSetAttribute(gemm_qkv,   cudaFuncAttributeMaxDynamicSharedMemorySize, SMEM_G);
    cudaFuncSetAttribute(scorenorm_h, cudaFuncAttributeMaxDynamicSharedMemorySize, SMEM_S);
    cudaFuncSetAttribute(ctx_h,      cudaFuncAttributeMaxDynamicSharedMemorySize, SMEM_C);

    f2h_all<<<8192, 256>>>(x, wq, wk, wv, wo, w1, w2,
                           pxh, pwqkvh, pwoh, pw1h, pw2h);

    gemm_qkv<<<dim3(3*CD/128, CM/128), 256, SMEM_G>>>(pxh, pwqkvh, bq, bk, bv,
                                                      pqh, pkh, pvh);

    scorenorm_h<<<dim3(CS/64, CS/32, CB), 256, SMEM_S>>>();
    ctx_h<<<dim3(CS/128, CB*CH), 256, SMEM_C>>>();

    const dim3 gDD(CD / 128, CM / 128);
    gemm_h<0, false><<<gDD, 256, SMEM_G>>>(pctxh, pwoh, bo, pt0, CM, CD, CD);
    ln_kernel<<<CM, 256>>>(x, pt0, g1, be1, px1, px1h);

    gemm_h<2, true ><<<dim3(CDFF/128, CM/128), 256, SMEM_G>>>(px1h, pw1h, b1, pffh, CM, CDFF, CD);
    gemm_h<0, false><<<gDD, 256, SMEM_G>>>(pffh, pw2h, b2, pt0, CM, CD, CDFF);
    ln_kernel<<<CM, 256>>>(px1, pt0, g2, be2, out, nullptr);
}

// round 15
// speedup vs baseline: 1.0806x; 1.0066x over previous
#include <cuda_runtime.h>
#include <cuda_fp16.h>
#include <cstdint>

constexpr int CB  = 2;
constexpr int CS  = 2048;
constexpr int CD  = 1024;
constexpr int CH  = 16;
constexpr int CDK = 64;
constexpr int CDFF= 4096;
constexpr int CM  = CB * CS;   // 4096

// ------------------------- scratch (device globals) --------------------------
__device__ __half g_xh [(size_t)CM*CD];
__device__ __half g_wqkvh[(size_t)CD*3*CD];
__device__ __half g_woh[(size_t)CD*CD];
__device__ __half g_w1h[(size_t)CD*CDFF];
__device__ __half g_w2h[(size_t)CDFF*CD];
__device__ __half g_qh [(size_t)CB*CH*CS*CDK];
__device__ __half g_kh [(size_t)CB*CH*CS*CDK];
__device__ __half g_vh [(size_t)CB*CH*CS*CDK];
__device__ __half g_Eh [(size_t)CB*CH*CS*CS];   // normalized attention weights
__device__ __half g_ctxh[(size_t)CM*CD];
__device__ __half g_x1h[(size_t)CM*CD];
__device__ __half g_ffh[(size_t)CM*CDFF];
__device__ float  g_t0 [(size_t)CM*CD];
__device__ float  g_x1 [(size_t)CM*CD];

// ------------------------- helpers ------------------------------------------
__device__ __forceinline__ float fast_exp(float x) {
    const float L2E = 1.4426950408889634f;
    float t = fmaf(x, L2E, 12582912.0f);
    int   e = __float_as_int(t) - 0x4B400000;
    float r = t - 12582912.0f;
    float f = fmaf(x, L2E, -r);
    float p =            1.3333558e-3f;
    p = fmaf(p, f, 9.6181291e-3f);
    p = fmaf(p, f, 5.5504109e-2f);
    p = fmaf(p, f, 2.4022651e-1f);
    p = fmaf(p, f, 6.9314718e-1f);
    p = fmaf(p, f, 1.0f);
    return __int_as_float(__float_as_int(p) + (e << 23));
}
__device__ __forceinline__ uint32_t smem_u32(const void* p) {
    uint32_t a;
    asm("{ .reg .u64 t; cvta.to.shared.u64 t, %1; cvt.u32.u64 %0, t; }" : "=r"(a) : "l"(p));
    return a;
}
__device__ __forceinline__ void cp16(uint32_t dst, const void* src) {
    asm volatile("cp.async.cg.shared.global [%0], [%1], 16;"
                 :: "r"(dst), "l"((unsigned long long)__cvta_generic_to_global(src)));
}
__device__ __forceinline__ void st16cs(void* p, uint4 v) {
    asm volatile("st.global.cs.v4.b32 [%0], {%1,%2,%3,%4};"
                 :: "l"(__cvta_generic_to_global(p)),
                    "r"(v.x), "r"(v.y), "r"(v.z), "r"(v.w) : "memory");
}
#define CP_COMMIT() asm volatile("cp.async.commit_group;" ::: "memory")
#define CP_WAIT(n)  asm volatile("cp.async.wait_group %0;" :: "n"(n) : "memory")

#define LDSM4(r, a) \
    asm volatile("ldmatrix.sync.aligned.m8n8.x4.shared.b16 {%0,%1,%2,%3}, [%4];" \
        : "=r"((r)[0]), "=r"((r)[1]), "=r"((r)[2]), "=r"((r)[3]) : "r"(a))
#define LDSM4T(r, a) \
    asm volatile("ldmatrix.sync.aligned.m8n8.x4.trans.shared.b16 {%0,%1,%2,%3}, [%4];" \
        : "=r"((r)[0]), "=r"((r)[1]), "=r"((r)[2]), "=r"((r)[3]) : "r"(a))
#define MMA16(c, a, b0, b1) \
    asm volatile("mma.sync.aligned.m16n8k16.row.col.f32.f16.f16.f32 " \
        "{%0,%1,%2,%3},{%4,%5,%6,%7},{%8,%9},{%0,%1,%2,%3};" \
        : "+f"((c)[0]), "+f"((c)[1]), "+f"((c)[2]), "+f"((c)[3]) \
        : "r"((a)[0]), "r"((a)[1]), "r"((a)[2]), "r"((a)[3]), "r"(b0), "r"(b1))

__device__ __forceinline__ uint32_t hmul2u(uint32_t a, uint32_t b) {
    __half2 r = __hmul2(*(__half2*)&a, *(__half2*)&b);
    return *(uint32_t*)&r;
}
__device__ __forceinline__ uint32_t packh2(float a, float b) {
    __half2 h = __floats2half2_rn(a, b);
    return *(uint32_t*)&h;
}

// ------------------------- fused f32 -> f16 convert --------------------------
__global__ void f2h_all(const float* __restrict__ x,
                        const float* __restrict__ wq, const float* __restrict__ wk,
                        const float* __restrict__ wv, const float* __restrict__ wo,
                        const float* __restrict__ w1, const float* __restrict__ w2,
                        __half* __restrict__ xh, __half* __restrict__ wqkvh,
                        __half* __restrict__ woh,
                        __half* __restrict__ w1h, __half* __restrict__ w2h)
{
    const size_t e8 = ((size_t)blockIdx.x * 256 + threadIdx.x) * 8;
    const float* s; __half* d; size_t off, dst;
    if (e8 < 4194304) { s = x; d = xh; off = e8; dst = off; }
    else if (e8 < 7340032) {
        const size_t o = e8 - 4194304;
        const int proj = (int)(o >> 20);
        off = o & 1048575;
        s = proj == 0 ? wq : (proj == 1 ? wk : wv);
        d = wqkvh;
        const size_t k = off >> 10, c = off & 1023;
        dst = k * 3072 + proj * 1024 + c;
    }
    else if (e8 <  8388608) { s = wo; d = woh; off = e8 - 7340032; dst = off; }
    else if (e8 < 12582912) { s = w1; d = w1h; off = e8 - 8388608; dst = off; }
    else                    { s = w2; d = w2h; off = e8 - 12582912; dst = off; }
    float4 u0 = *(const float4*)(s + off);
    float4 u1 = *(const float4*)(s + off + 4);
    __half2 h0 = __floats2half2_rn(u0.x, u0.y);
    __half2 h1 = __floats2half2_rn(u0.z, u0.w);
    __half2 h2 = __floats2half2_rn(u1.x, u1.y);
    __half2 h3 = __floats2half2_rn(u1.z, u1.w);
    uint4 o;
    o.x = *(uint32_t*)&h0; o.y = *(uint32_t*)&h1;
    o.z = *(uint32_t*)&h2; o.w = *(uint32_t*)&h3;
    *(uint4*)(d + dst) = o;
}

// ------------------------- shared dense mainloop (BK=64) ---------------------
constexpr int G_AST = 72, G_BST = 136;
constexpr int G_ASZ = 128 * G_AST, G_BSZ = 64 * G_BST;
constexpr int G_STG = G_ASZ + G_BSZ;

__device__ __forceinline__ void g_issue(uint32_t smb, int tid, int kt,
                                        const __half* A, const __half* W,
                                        int K, int N, int bm, int bn)
{
    const int st = kt % 3;
    const __half* As = A + (size_t)bm * K + kt * 64;
    const __half* Ws = W + (size_t)(kt * 64) * N + bn;
    #pragma unroll
    for (int i = 0; i < 4; i++) {
        const int c = i * 256 + tid;
        const int r = c >> 3, h8 = (c & 7) * 8;
        cp16(smb + (st * G_STG + r * G_AST + h8) * 2, As + (size_t)r * K + h8);
    }
    #pragma unroll
    for (int i = 0; i < 4; i++) {
        const int c = i * 256 + tid;
        const int kk = c >> 4, n8 = (c & 15) * 8;
        cp16(smb + (st * G_STG + G_ASZ + kk * G_BST + n8) * 2, Ws + (size_t)kk * N + n8);
    }
}

// fragment-pipelined compute: prefetch step s+1 fragments between the two
// halves of step s's MMAs so LDSM latency hides under tensor issue.
__device__ __forceinline__ void g_ldfrag(uint32_t stA, uint32_t stB, int kk16,
                                         int lane, int wm, int wn,
                                         uint32_t a[2][4], uint32_t b[8][2])
{
    #pragma unroll
    for (int mi = 0; mi < 2; mi++) {
        const uint32_t ad = stA +
            ((wm * 32 + mi * 16 + (lane & 15)) * G_AST + kk16 + (lane >> 4) * 8) * 2;
        LDSM4(a[mi], ad);
    }
    #pragma unroll
    for (int p = 0; p < 4; p++) {
        const int n0 = wn * 64 + p * 16;
        const uint32_t ad = stB +
            ((kk16 + (lane & 7) + ((lane >> 3) & 1) * 8) * G_BST + n0 + (lane >> 4) * 8) * 2;
        uint32_t r[4];
        LDSM4T(r, ad);
        b[2*p  ][0] = r[0]; b[2*p  ][1] = r[1];
        b[2*p+1][0] = r[2]; b[2*p+1][1] = r[3];
    }
}

__device__ __forceinline__ void g_compute(uint32_t smb, int kt, int lane,
                                          int wm, int wn, float acc[2][8][4])
{
    const uint32_t stA = smb + (kt % 3) * G_STG * 2;
    const uint32_t stB = stA + G_ASZ * 2;
    uint32_t aF[2][2][4], bF[2][8][2];
    g_ldfrag(stA, stB, 0, lane, wm, wn, aF[0], bF[0]);
    #pragma unroll
    for (int s = 0; s < 4; s++) {
        const int cur = s & 1, nxt = cur ^ 1;
        // first half of MMAs
        #pragma unroll
        for (int mi = 0; mi < 2; mi++)
            #pragma unroll
            for (int ni = 0; ni < 4; ni++)
                MMA16(acc[mi][ni], aF[cur][mi], bF[cur][ni][0], bF[cur][ni][1]);
        // prefetch next step's fragments
        if (s < 3) g_ldfrag(stA, stB, (s + 1) * 16, lane, wm, wn, aF[nxt], bF[nxt]);
        // second half of MMAs
        #pragma unroll
        for (int mi = 0; mi < 2; mi++)
            #pragma unroll
            for (int ni = 4; ni < 8; ni++)
                MMA16(acc[mi][ni], aF[cur][mi], bF[cur][ni][0], bF[cur][ni][1]);
    }
}

// ======================= dense GEMM fp16 (BK=64, 3-stage) ====================
template<int OMODE, bool RELU>       // 0: fp32 rm, 2: fp16 rm
__global__ __launch_bounds__(256, 2)
void gemm_h(const __half* __restrict__ A, const __half* __restrict__ W,
            const float* __restrict__ bias, void* __restrict__ Cout,
            int M, int N, int K)
{
    extern __shared__ __half sh[];
    const uint32_t smb = smem_u32(sh);
    const int tid = threadIdx.x, wid = tid >> 5, lane = tid & 31;
    const int wm = wid >> 1, wn = wid & 1;
    const int gid = lane >> 2, tig = lane & 3;
    const int bm = blockIdx.y * 128, bn = blockIdx.x * 128;

    float acc[2][8][4] = {};
    const int nt = K / 64;
    g_issue(smb, tid, 0, A, W, K, N, bm, bn); CP_COMMIT();
    g_issue(smb, tid, 1, A, W, K, N, bm, bn); CP_COMMIT();

    for (int kt = 0; kt < nt; kt++) {
        CP_WAIT(1);
        __syncthreads();
        if (kt + 2 < nt) g_issue(smb, tid, kt + 2, A, W, K, N, bm, bn);
        CP_COMMIT();
        g_compute(smb, kt, lane, wm, wn, acc);
    }

    #pragma unroll
    for (int mi = 0; mi < 2; mi++) {
        #pragma unroll
        for (int ni = 0; ni < 8; ni++) {
            const int row = bm + wm * 32 + mi * 16 + gid;
            const int col = bn + wn * 64 + ni * 8 + tig * 2;
            const float2 b2 = *(const float2*)(bias + col);
            float v0 = acc[mi][ni][0] + b2.x, v1 = acc[mi][ni][1] + b2.y;
            float v2 = acc[mi][ni][2] + b2.x, v3 = acc[mi][ni][3] + b2.y;
            if (RELU) { v0 = fmaxf(v0, 0.f); v1 = fmaxf(v1, 0.f);
                        v2 = fmaxf(v2, 0.f); v3 = fmaxf(v3, 0.f); }
            if (OMODE == 0) {
                float* C = (float*)Cout;
                *(float2*)(C + (size_t)row       * N + col) = make_float2(v0, v1);
                *(float2*)(C + (size_t)(row + 8) * N + col) = make_float2(v2, v3);
            } else {
                __half* C = (__half*)Cout;
                *(__half2*)(C + (size_t)row       * N + col) = __floats2half2_rn(v0, v1);
                *(__half2*)(C + (size_t)(row + 8) * N + col) = __floats2half2_rn(v2, v3);
            }
        }
    }
}

// ======================= fused QKV GEMM (N=3072) =============================
__global__ __launch_bounds__(256, 2)
void gemm_qkv(const __half* __restrict__ A, const __half* __restrict__ W,
              const float* __restrict__ bq, const float* __restrict__ bk,
              const float* __restrict__ bv,
              __half* __restrict__ Oq, __half* __restrict__ Ok,
              __half* __restrict__ Ov)
{
    constexpr int K = CD, N = 3 * CD;
    extern __shared__ __half sh[];
    const uint32_t smb = smem_u32(sh);
    const int tid = threadIdx.x, wid = tid >> 5, lane = tid & 31;
    const int wm = wid >> 1, wn = wid & 1;
    const int gid = lane >> 2, tig = lane & 3;
    const int bm = blockIdx.y * 128, bn = blockIdx.x * 128;

    float acc[2][8][4] = {};
    const int nt = K / 64;
    g_issue(smb, tid, 0, A, W, K, N, bm, bn); CP_COMMIT();
    g_issue(smb, tid, 1, A, W, K, N, bm, bn); CP_COMMIT();

    for (int kt = 0; kt < nt; kt++) {
        CP_WAIT(1);
        __syncthreads();
        if (kt + 2 < nt) g_issue(smb, tid, kt + 2, A, W, K, N, bm, bn);
        CP_COMMIT();
        g_compute(smb, kt, lane, wm, wn, acc);
    }

    const int cb = bn + wn * 64;
    const int proj = cb >> 10;
    const int h = (cb >> 6) & 15;
    __half* O = proj == 0 ? Oq : (proj == 1 ? Ok : Ov);
    const float* bs = proj == 0 ? bq : (proj == 1 ? bk : bv);
    #pragma unroll
    for (int mi = 0; mi < 2; mi++) {
        #pragma unroll
        for (int ni = 0; ni < 8; ni++) {
            const int row = bm + wm * 32 + mi * 16 + gid;
            const int dk = ni * 8 + tig * 2;
            const float2 b2 = *(const float2*)(bs + h * 64 + dk);
            const int b = row >> 11, s1 = row & (CS - 1);
            const size_t base = (((size_t)(b * CH + h)) * CS + s1) * CDK + dk;
            *(__half2*)(O + base) =
                __floats2half2_rn(acc[mi][ni][0] + b2.x, acc[mi][ni][1] + b2.y);
            *(__half2*)(O + base + (size_t)8 * CDK) =
                __floats2half2_rn(acc[mi][ni][2] + b2.x, acc[mi][ni][3] + b2.y);
        }
    }
}

// ======================= scores: normalized E, coalesced store ===============
__global__ __launch_bounds__(256, 2)
void scorenorm_h()
{
    constexpr int QST = 72;
    constexpr int QSZ = 32 * QST, KSZ = 64 * QST, STG = QSZ + KSZ;  // 6912 halves
    constexpr int EBUF = 32 * 72;
    extern __shared__ __half sh[];
    const uint32_t smb = smem_u32(sh);

    const int tid = threadIdx.x, wid = tid >> 5, lane = tid & 31;
    const int wm = wid >> 2, wn = wid & 3;       // 2 m-warps x 4 n-warps
    const int gid = lane >> 2, tig = lane & 3;
    const int b = blockIdx.z;
    const int q0 = blockIdx.y * 32, k0 = blockIdx.x * 64;
    const size_t plane = (size_t)CS * CS;

    auto issue = [&](int h) {
        const int st = h & 1;
        const __half* qb = g_qh + (((size_t)(b * CH + h)) * CS + q0) * CDK;
        const __half* kb = g_kh + (((size_t)(b * CH + h)) * CS + k0) * CDK;
        {
            const int r = tid >> 3, h8 = (tid & 7) * 8;
            cp16(smb + (st * STG + r * QST + h8) * 2, qb + (size_t)r * CDK + h8);
        }
        #pragma unroll
        for (int i = 0; i < 2; i++) {
            const int c = i * 256 + tid;
            const int r = c >> 3, h8 = (c & 7) * 8;
            cp16(smb + (st * STG + QSZ + r * QST + h8) * 2, kb + (size_t)r * CDK + h8);
        }
    };

    uint32_t Ereg[CH][4];
    float sum[8] = {};

    issue(0); CP_COMMIT();

    #pragma unroll
    for (int h = 0; h < CH; h++) {
        if (h + 1 < CH) { issue(h + 1); CP_COMMIT(); CP_WAIT(1); }
        else            { CP_WAIT(0); }
        __syncthreads();

        const uint32_t stQ = smb + (h & 1) * STG * 2;
        const uint32_t stK = stQ + QSZ * 2;

        float acc[8] = {};
        #pragma unroll
        for (int c16 = 0; c16 < 4; c16++) {
            const int kk16 = c16 * 16;
            uint32_t a[4], r[4];
            LDSM4(a, stQ + ((wm * 16 + (lane & 15)) * QST + kk16 + (lane >> 4) * 8) * 2);
            LDSM4(r, stK + ((wn * 16 + (lane & 15)) * QST + kk16 + (lane >> 4) * 8) * 2);
            MMA16(acc + 0, a, r[0], r[2]);
            MMA16(acc + 4, a, r[1], r[3]);
        }

        float e[8];
        #pragma unroll
        for (int j = 0; j < 8; j++) { e[j] = fast_exp(acc[j] * 0.125f); sum[j] += e[j]; }
        Ereg[h][0] = packh2(e[0], e[1]);
        Ereg[h][1] = packh2(e[2], e[3]);
        Ereg[h][2] = packh2(e[4], e[5]);
        Ereg[h][3] = packh2(e[6], e[7]);
        __syncthreads();
    }

    uint32_t rdh2[4];
    rdh2[0] = packh2(1.0f / sum[0], 1.0f / sum[1]);
    rdh2[1] = packh2(1.0f / sum[2], 1.0f / sum[3]);
    rdh2[2] = packh2(1.0f / sum[4], 1.0f / sum[5]);
    rdh2[3] = packh2(1.0f / sum[6], 1.0f / sum[7]);

    const int ql = wm * 16 + gid;
    const int kl = wn * 16 + tig * 2;
    const int srow = tid >> 3, scol = (tid & 7) * 8;
    #pragma unroll
    for (int h = 0; h < CH; h++) {
        __half* eb0 = sh + 2 * STG + (h & 1) * EBUF;
        *(uint32_t*)(eb0 + ql      * 72 + kl    ) = hmul2u(Ereg[h][0], rdh2[0]);
        *(uint32_t*)(eb0 + (ql + 8)* 72 + kl    ) = hmul2u(Ereg[h][1], rdh2[1]);
        *(uint32_t*)(eb0 + ql      * 72 + kl + 8) = hmul2u(Ereg[h][2], rdh2[2]);
        *(uint32_t*)(eb0 + (ql + 8)* 72 + kl + 8) = hmul2u(Ereg[h][3], rdh2[3]);
        __syncthreads();
        __half* Eb = g_Eh + ((size_t)(b * CH + h)) * plane;
        uint4 v = *(uint4*)(eb0 + srow * 72 + scol);
        st16cs(Eb + (size_t)(q0 + srow) * CS + k0 + scol, v);
    }
}

// ======================= ctx: E_norm @ V, BK=64, 4-stage =====================
__global__ __launch_bounds__(256, 2)
void ctx_h()
{
    constexpr int EST = 72, VST = 72;
    constexpr int ESZ = 128 * EST, VSZ = 64 * VST;
    constexpr int STG = ESZ + VSZ;                          // 13824 halves
    extern __shared__ __half sh[];
    const uint32_t smb = smem_u32(sh);

    const int tid = threadIdx.x, wid = tid >> 5, lane = tid & 31;
    const int wm = wid >> 1, wn = wid & 1;
    const int gid = lane >> 2, tig = lane & 3;
    const int bh = blockIdx.y;
    const int b = bh >> 4, h = bh & 15;
    const int q0 = blockIdx.x * 128;
    const size_t plane = (size_t)CS * CS;
    const __half* eb = g_Eh + (size_t)bh * plane;
    const __half* vb = g_vh + (size_t)bh * CS * CDK;

    auto issue = [&](int kt) {
        const int st = kt & 3;
        const int kb = kt * 64;
        #pragma unroll
        for (int i = 0; i < 4; i++) {
            const int c = i * 256 + tid;
            const int r = c >> 3, h8 = (c & 7) * 8;
            cp16(smb + (st * STG + r * EST + h8) * 2, eb + (size_t)(q0 + r) * CS + kb + h8);
        }
        #pragma unroll
        for (int i = 0; i < 2; i++) {
            const int c = i * 256 + tid;
            const int kk = c >> 3, n8 = (c & 7) * 8;
            cp16(smb + (st * STG + ESZ + kk * VST + n8) * 2, vb + (size_t)(kb + kk) * CDK + n8);
        }
    };

    float acc[2][4][4] = {};
    const int nt = CS / 64;
    issue(0); CP_COMMIT();
    issue(1); CP_COMMIT();
    issue(2); CP_COMMIT();

    for (int kt = 0; kt < nt; kt++) {
        CP_WAIT(2);
        __syncthreads();
        if (kt + 3 < nt) issue(kt + 3);
        CP_COMMIT();

        const uint32_t stE = smb + (kt & 3) * STG * 2;
        const uint32_t stV = stE + ESZ * 2;
        #pragma unroll
        for (int h16 = 0; h16 < 4; h16++) {
            const int kk16 = h16 * 16;
            uint32_t a[2][4], bv[4][2];
            #pragma unroll
            for (int mi = 0; mi < 2; mi++) {
                const uint32_t ad = stE +
                    ((wm * 32 + mi * 16 + (lane & 15)) * EST + kk16 + (lane >> 4) * 8) * 2;
                LDSM4(a[mi], ad);
            }
            #pragma unroll
            for (int p = 0; p < 2; p++) {
                const int n0 = wn * 32 + p * 16;
                const uint32_t ad = stV +
                    ((kk16 + (lane & 7) + ((lane >> 3) & 1) * 8) * VST + n0 + (lane >> 4) * 8) * 2;
                uint32_t r[4];
                LDSM4T(r, ad);
                bv[2*p  ][0] = r[0]; bv[2*p  ][1] = r[1];
                bv[2*p+1][0] = r[2]; bv[2*p+1][1] = r[3];
            }
            #pragma unroll
            for (int mi = 0; mi < 2; mi++)
                #pragma unroll
                for (int ni = 0; ni < 4; ni++)
                    MMA16(acc[mi][ni], a[mi], bv[ni][0], bv[ni][1]);
        }
    }

    #pragma unroll
    for (int mi = 0; mi < 2; mi++) {
        #pragma unroll
        for (int ni = 0; ni < 4; ni++) {
            const int q = q0 + wm * 32 + mi * 16 + gid;
            const int n = wn * 32 + ni * 8 + tig * 2;
            __half* p0p = g_ctxh + (((size_t)(b * CS + q    )) * CH + h) * CDK + n;
            __half* p1p = g_ctxh + (((size_t)(b * CS + q + 8)) * CH + h) * CDK + n;
            *(__half2*)p0p = __floats2half2_rn(acc[mi][ni][0], acc[mi][ni][1]);
            *(__half2*)p1p = __floats2half2_rn(acc[mi][ni][2], acc[mi][ni][3]);
        }
    }
}

// ------------------------- residual + LayerNorm ------------------------------
__global__ void ln_kernel(const float* __restrict__ A, const float* __restrict__ Bp,
                          const float* __restrict__ g, const float* __restrict__ be,
                          float* __restrict__ out, __half* __restrict__ outh)
{
    const int row = blockIdx.x;
    const int tid = threadIdx.x;
    const int i0 = tid << 2;
    float4 a  = *(const float4*)(A  + (size_t)row*CD + i0);
    float4 bb = *(const float4*)(Bp + (size_t)row*CD + i0);
    const float v0 = a.x + bb.x, v1 = a.y + bb.y, v2 = a.z + bb.z, v3 = a.w + bb.w;
    float s  = v0 + v1 + v2 + v3;
    float ss = v0*v0 + v1*v1 + v2*v2 + v3*v3;
    #pragma unroll
    for (int o = 16; o; o >>= 1) {
        s  += __shfl_xor_sync(0xffffffffu, s,  o);
        ss += __shfl_xor_sync(0xffffffffu, ss, o);
    }
    __shared__ float sh1[8], sh2[8];
    if ((tid & 31) == 0) { sh1[tid >> 5] = s; sh2[tid >> 5] = ss; }
    __syncthreads();
    s = 0.f; ss = 0.f;
    #pragma unroll
    for (int w = 0; w < 8; w++) { s += sh1[w]; ss += sh2[w]; }
    const float mean = s * (1.0f / CD);
    const float var  = ss * (1.0f / CD) - mean * mean;
    const float rstd = rsqrtf(var + 1e-5f);
    float4 gg = *(const float4*)(g  + i0);
    float4 bt = *(const float4*)(be + i0);
    float4 o4;
    o4.x = (v0 - mean) * rstd * gg.x + bt.x;
    o4.y = (v1 - mean) * rstd * gg.y + bt.y;
    o4.z = (v2 - mean) * rstd * gg.z + bt.z;
    o4.w = (v3 - mean) * rstd * gg.w + bt.w;
    *(float4*)(out + (size_t)row*CD + i0) = o4;
    if (outh) {
        __half2 h0 = __floats2half2_rn(o4.x, o4.y);
        __half2 h1 = __floats2half2_rn(o4.z, o4.w);
        uint2 u; u.x = *(uint32_t*)&h0; u.y = *(uint32_t*)&h1;
        *(uint2*)(outh + (size_t)row*CD + i0) = u;
    }
}

// ------------------------- launch -------------------------------------------
extern "C" void kernel_launch(void* const* d_in, const int* in_sizes, int n_in,
                              void* d_out, int out_size)
{
    (void)in_sizes; (void)n_in; (void)out_size;
    const float* x   = (const float*)d_in[0];
    const float* wq  = (const float*)d_in[1];
    const float* bq  = (const float*)d_in[2];
    const float* wk  = (const float*)d_in[3];
    const float* bk  = (const float*)d_in[4];
    const float* wv  = (const float*)d_in[5];
    const float* bv  = (const float*)d_in[6];
    const float* wo  = (const float*)d_in[7];
    const float* bo  = (const float*)d_in[8];
    const float* g1  = (const float*)d_in[9];
    const float* be1 = (const float*)d_in[10];
    const float* w1  = (const float*)d_in[11];
    const float* b1  = (const float*)d_in[12];
    const float* w2  = (const float*)d_in[13];
    const float* b2  = (const float*)d_in[14];
    const float* g2  = (const float*)d_in[15];
    const float* be2 = (const float*)d_in[16];
    float* out = (float*)d_out;

    __half *pxh, *pwqkvh, *pwoh, *pw1h, *pw2h;
    __half *pqh, *pkh, *pvh, *pctxh, *px1h, *pffh;
    float *pt0, *px1;
    cudaGetSymbolAddress((void**)&pxh,    g_xh);
    cudaGetSymbolAddress((void**)&pwqkvh, g_wqkvh);
    cudaGetSymbolAddress((void**)&pwoh,   g_woh);
    cudaGetSymbolAddress((void**)&pw1h,   g_w1h);
    cudaGetSymbolAddress((void**)&pw2h,   g_w2h);
    cudaGetSymbolAddress((void**)&pqh,    g_qh);
    cudaGetSymbolAddress((void**)&pkh,    g_kh);
    cudaGetSymbolAddress((void**)&pvh,    g_vh);
    cudaGetSymbolAddress((void**)&pctxh,  g_ctxh);
    cudaGetSymbolAddress((void**)&px1h,   g_x1h);
    cudaGetSymbolAddress((void**)&pffh,   g_ffh);
    cudaGetSymbolAddress((void**)&pt0,    g_t0);
    cudaGetSymbolAddress((void**)&px1,    g_x1);

    const int SMEM_G = 3 * G_STG * 2;                        // 107520
    const int SMEM_S = (2 * (96 * 72) + 2 * (32 * 72)) * 2;  // 36864
    const int SMEM_C = 4 * (128 * 72 + 64 * 72) * 2;         // 110592
    cudaFuncSetAttribute(gemm_h<0,false>, cudaFuncAttributeMaxDynamicSharedMemorySize, SMEM_G);
    cudaFuncSetAttribute(gemm_h<2,true >, cudaFuncAttributeMaxDynamicSharedMemorySize, SMEM_G);
    cudaFuncSetAttribute(gemm_qkv,   cudaFuncAttributeMaxDynamicSharedMemorySize, SMEM_G);
    cudaFuncSetAttribute(scorenorm_h, cudaFuncAttributeMaxDynamicSharedMemorySize, SMEM_S);
    cudaFuncSetAttribute(ctx_h,      cudaFuncAttributeMaxDynamicSharedMemorySize, SMEM_C);

    f2h_all<<<8192, 256>>>(x, wq, wk, wv, wo, w1, w2,
                           pxh, pwqkvh, pwoh, pw1h, pw2h);

    gemm_qkv<<<dim3(3*CD/128, CM/128), 256, SMEM_G>>>(pxh, pwqkvh, bq, bk, bv,
                                                      pqh, pkh, pvh);

    scorenorm_h<<<dim3(CS/64, CS/32, CB), 256, SMEM_S>>>();
    ctx_h<<<dim3(CS/128, CB*CH), 256, SMEM_C>>>();

    const dim3 gDD(CD / 128, CM / 128);
    gemm_h<0, false><<<gDD, 256, SMEM_G>>>(pctxh, pwoh, bo, pt0, CM, CD, CD);
    ln_kernel<<<CM, 256>>>(x, pt0, g1, be1, px1, px1h);

    gemm_h<2, true ><<<dim3(CDFF/128, CM/128), 256, SMEM_G>>>(px1h, pw1h, b1, pffh, CM, CDFF, CD);
    gemm_h<0, false><<<gDD, 256, SMEM_G>>>(pffh, pw2h, b2, pt0, CM, CD, CDFF);
    ln_kernel<<<CM, 256>>>(px1, pt0, g2, be2, out, nullptr);
}